// round 1
// baseline (speedup 1.0000x reference)
#include <cuda_runtime.h>

#define N 384
#define D 512
#define MARGIN 0.5f
#define EPS 1e-6f

// Scratch: pairwise distances, only same-label entries are ever written/read.
// __device__ globals are zero-initialized at module load; unwritten entries
// stay 0 forever (loss_kernel never reads them unmasked).
__device__ float g_dist[N * N];

// One warp per (i, j) pair. Early-exit when labels differ (only same-label
// pairs are ever consumed downstream).
__global__ void dist_kernel(const float* __restrict__ f,
                            const int* __restrict__ labels) {
    int warp = (blockIdx.x * blockDim.x + threadIdx.x) >> 5;
    int lane = threadIdx.x & 31;
    if (warp >= N * N) return;
    int i = warp / N;
    int j = warp - i * N;
    if (labels[i] != labels[j]) return;

    const float* __restrict__ fi = f + i * D;
    const float* __restrict__ fj = f + j * D;
    float acc = 0.0f;
#pragma unroll
    for (int t = 0; t < D / 32; t++) {
        int idx = t * 32 + lane;          // coalesced 128B per step
        float d = fi[idx] - fj[idx] + EPS; // torch pairwise_distance eps
        acc = fmaf(d, d, acc);
    }
#pragma unroll
    for (int o = 16; o; o >>= 1) acc += __shfl_xor_sync(0xffffffffu, acc, o);
    if (lane == 0) g_dist[warp] = sqrtf(acc);
}

__global__ void zero_kernel(float* out) { out[0] = 0.0f; }

// One block per anchor i; thread j is positive-candidate j and loops over all
// negative candidates k. Per-anchor mean of hinge over (pos, neg) pairs.
__global__ void loss_kernel(const int* __restrict__ labels,
                            const int* __restrict__ levels,
                            float* __restrict__ out) {
    __shared__ float s_dist[N];
    __shared__ int   s_lab[N];
    __shared__ int   s_lev[N];
    __shared__ float s_sum;
    __shared__ int   s_npos;
    __shared__ int   s_nneg;

    const int i = blockIdx.x;
    const int j = threadIdx.x;

    if (j == 0) { s_sum = 0.0f; s_npos = 0; s_nneg = 0; }
    s_dist[j] = g_dist[i * N + j];
    s_lab[j]  = labels[j];
    s_lev[j]  = levels[j];
    __syncthreads();

    const int lab_i = s_lab[i];
    const int lev_i = s_lev[i];
    const bool same   = (j != i) && (s_lab[j] == lab_i);
    const bool is_pos = same && (s_lev[j] == lev_i);
    const bool is_neg = same && (s_lev[j] != lev_i);
    if (is_pos) atomicAdd(&s_npos, 1);
    if (is_neg) atomicAdd(&s_nneg, 1);

    float acc = 0.0f;
    if (is_pos) {
        const float dij = s_dist[j];
        for (int k = 0; k < N; k++) {
            bool neg_k = (k != i) && (s_lab[k] == lab_i) && (s_lev[k] != lev_i);
            if (neg_k) acc += fmaxf(dij - s_dist[k] + MARGIN, 0.0f);
        }
    }
    if (acc != 0.0f) atomicAdd(&s_sum, acc);
    __syncthreads();

    if (j == 0) {
        long long cnt = (long long)s_npos * (long long)s_nneg;
        if (cnt > 0) {
            atomicAdd(out, s_sum / (float)cnt * (1.0f / (float)N));
        }
    }
}

extern "C" void kernel_launch(void* const* d_in, const int* in_sizes, int n_in,
                              void* d_out, int out_size) {
    const float* features = (const float*)d_in[0];
    const int*   labels   = (const int*)d_in[1];
    const int*   levels   = (const int*)d_in[2];
    float* out = (float*)d_out;

    // 1 warp per (i,j) pair -> N*N warps
    const int total_threads = N * N * 32;
    const int block = 256;
    dist_kernel<<<(total_threads + block - 1) / block, block>>>(features, labels);
    zero_kernel<<<1, 1>>>(out);
    loss_kernel<<<N, N>>>(labels, levels, out);
}

// round 2
// speedup vs baseline: 3.6287x; 3.6287x over previous
#include <cuda_runtime.h>

#define N 384
#define D 512
#define MARGIN 0.5f
#define EPS 1e-6f

// Cross-block reduction scratch. Zero-initialized at module load; the last
// block of every launch resets them, so every graph replay starts clean.
__device__ float g_acc;
__device__ int   g_count;

__global__ __launch_bounds__(N) void triplet_fused_kernel(
    const float* __restrict__ features,
    const int*   __restrict__ labels,
    const int*   __restrict__ levels,
    float*       __restrict__ out) {
    __shared__ int   s_lab[N];
    __shared__ int   s_lev[N];
    __shared__ float s_dist[N];   // only same-label entries written/read
    __shared__ int   s_same[N];   // compacted same-label indices
    __shared__ int   s_negl[N];   // compacted negative indices
    __shared__ int   s_nsame, s_nneg, s_npos;
    __shared__ float s_sum;

    const int i = blockIdx.x;
    const int t = threadIdx.x;

    if (t == 0) { s_nsame = 0; s_nneg = 0; s_npos = 0; s_sum = 0.0f; }
    s_lab[t] = labels[t];
    s_lev[t] = levels[t];
    __syncthreads();

    const int lab_i = s_lab[i];
    const int lev_i = s_lev[i];
    const bool same = (t != i) && (s_lab[t] == lab_i);
    if (same) {
        int p = atomicAdd(&s_nsame, 1);
        s_same[p] = t;
        if (s_lev[t] != lev_i) {
            int q = atomicAdd(&s_nneg, 1);
            s_negl[q] = t;
        } else {
            atomicAdd(&s_npos, 1);
        }
    }
    __syncthreads();

    // Distances: warp w handles same-label entries w, w+12, ...
    const int wid  = t >> 5;
    const int lane = t & 31;
    const int nw   = blockDim.x >> 5;  // 12 warps
    const float4* __restrict__ fi = (const float4*)(features + i * D);
    const int nsame = s_nsame;
    for (int m = wid; m < nsame; m += nw) {
        const int j = s_same[m];
        const float4* __restrict__ fj = (const float4*)(features + j * D);
        float acc = 0.0f;
#pragma unroll
        for (int u = 0; u < 4; u++) {
            const int idx = u * 32 + lane;   // coalesced 512B/step per warp
            float4 a = fi[idx];
            float4 b = fj[idx];
            float d0 = a.x - b.x + EPS;      // torch pairwise_distance eps
            float d1 = a.y - b.y + EPS;
            float d2 = a.z - b.z + EPS;
            float d3 = a.w - b.w + EPS;
            acc = fmaf(d0, d0, acc);
            acc = fmaf(d1, d1, acc);
            acc = fmaf(d2, d2, acc);
            acc = fmaf(d3, d3, acc);
        }
#pragma unroll
        for (int o = 16; o; o >>= 1) acc += __shfl_xor_sync(0xffffffffu, acc, o);
        if (lane == 0) s_dist[j] = sqrtf(acc);
    }
    __syncthreads();

    // Hinge loss: thread t (if positive) loops over compacted negatives.
    const bool is_pos = same && (s_lev[t] == lev_i);
    float acc = 0.0f;
    if (is_pos) {
        const float dij = s_dist[t];
        const int nn = s_nneg;
        for (int q = 0; q < nn; q++) {
            acc += fmaxf(dij - s_dist[s_negl[q]] + MARGIN, 0.0f);
        }
    }
    if (acc != 0.0f) atomicAdd(&s_sum, acc);
    __syncthreads();

    // Per-anchor contribution + last-block finalize.
    if (t == 0) {
        float contrib = 0.0f;
        const long long cnt = (long long)s_npos * (long long)s_nneg;
        if (cnt > 0) contrib = s_sum / (float)cnt * (1.0f / (float)N);
        atomicAdd(&g_acc, contrib);
        __threadfence();
        const int ticket = atomicAdd(&g_count, 1);
        if (ticket == (int)gridDim.x - 1) {
            out[0] = atomicExch(&g_acc, 0.0f);  // read final sum, reset for replay
            g_count = 0;
        }
    }
}

extern "C" void kernel_launch(void* const* d_in, const int* in_sizes, int n_in,
                              void* d_out, int out_size) {
    const float* features = (const float*)d_in[0];
    const int*   labels   = (const int*)d_in[1];
    const int*   levels   = (const int*)d_in[2];
    float* out = (float*)d_out;

    triplet_fused_kernel<<<N, N>>>(features, labels, levels, out);
}